// round 2
// baseline (speedup 1.0000x reference)
#include <cuda_runtime.h>
#include <math.h>

// ---------------------------------------------------------------------------
// KANConvNet: 3 KAN conv layers + KAN classifier head.
// Layer l: unfold(k,s,p) -> kan_linear(in=cin*k*k, out) -> relu -> (maxpool 2x2)
//   L0: cin=3,  cout=16, k=7, s=2, p=3 : 224 -> 112 -> pool 56
//   L1: cin=16, cout=32, k=3, s=2, p=1 : 56  -> 28  -> pool 14
//   L2: cin=32, cout=64, k=3, s=2, p=1 : 14  -> 7   (no pool)
// head: mean(7x7) -> kan_linear(64 -> 200)
// kan_linear: y = silu(x) @ Wb^T + sum_k B_k(x) * (Ws*scaler)  (9 features / input)
// B-splines: cubic, uniform knots t_j = -2.2 + 0.4*j, j=0..11, 8 bases.
// ---------------------------------------------------------------------------

// Packed weights: wp[o][i*9 + 0] = base_w[o][i]; wp[o][i*9+1+k] = sw[o][i][k]*sc[o][i]
// Row length padded to FP (multiple of 4 floats) for float4 GEMM.
#define FP0 1324   // 147*9 = 1323 -> 1324
#define FP1 1296   // 144*9
#define FP2 2592   // 288*9
#define FPC 576    // 64*9

__device__ float g_wp0[16  * FP0];
__device__ float g_wp1[32  * FP1];
__device__ float g_wp2[64  * FP2];
__device__ float g_wpc[200 * FPC];

__device__ float g_a0[8 * 16 * 112 * 112];
__device__ float g_p0[8 * 16 * 56 * 56];
__device__ float g_a1[8 * 32 * 28 * 28];
__device__ float g_p1[8 * 32 * 14 * 14];
__device__ float g_a2[8 * 64 * 7 * 7];

// ---------------------------------------------------------------------------
// phi(x): [silu(x), B0..B7]  (uniform cubic B-spline, closed form)
// ---------------------------------------------------------------------------
__device__ __forceinline__ void eval_phi(float x, float* ph) {
    float sig = 1.0f / (1.0f + expf(-x));
    ph[0] = x * sig;
#pragma unroll
    for (int j = 0; j < 8; j++) ph[1 + j] = 0.0f;

    float t  = (x + 2.2f) * 2.5f;       // (x - t0) / h
    float mf = floorf(t);
    int   m  = (int)mf;
    if (m >= 0 && m <= 10) {
        float u  = t - mf;
        float u2 = u * u;
        float u3 = u2 * u;
        float om = 1.0f - u;
        float w0 = (1.0f / 6.0f) * om * om * om;
        float w1 = (1.0f / 6.0f) * (3.0f * u3 - 6.0f * u2 + 4.0f);
        float w2 = (1.0f / 6.0f) * (-3.0f * u3 + 3.0f * u2 + 3.0f * u + 1.0f);
        float w3 = (1.0f / 6.0f) * u3;
        int j0 = m - 3;
        if (j0     >= 0 && j0     < 8) ph[1 + j0]     = w0;
        if (j0 + 1 >= 0 && j0 + 1 < 8) ph[1 + j0 + 1] = w1;
        if (j0 + 2 >= 0 && j0 + 2 < 8) ph[1 + j0 + 2] = w2;
        if (j0 + 3 >= 0 && j0 + 3 < 8) ph[1 + j0 + 3] = w3;
    }
}

// ---------------------------------------------------------------------------
// Weight packing: one thread per packed element.
// ---------------------------------------------------------------------------
__global__ void pack_kernel(const float* __restrict__ bw,
                            const float* __restrict__ sw,
                            const float* __restrict__ sc,
                            float* __restrict__ wp,
                            int OUT, int IN, int FPr) {
    int idx = blockIdx.x * blockDim.x + threadIdx.x;
    int total = OUT * FPr;
    if (idx >= total) return;
    int o = idx / FPr;
    int f = idx - o * FPr;
    float v = 0.0f;
    if (f < IN * 9) {
        int i = f / 9;
        int r = f - i * 9;
        int oi = o * IN + i;
        if (r == 0) v = bw[oi];
        else        v = sw[oi * 8 + (r - 1)] * sc[oi];
    }
    wp[idx] = v;
}

// ---------------------------------------------------------------------------
// Fused KAN conv layer: unfold + phi + GEMM + relu.
// Block: 256 threads, 16 positions x 16 outputs (blockIdx.y selects out tile).
// ---------------------------------------------------------------------------
template <int CIN, int K, int S, int P, int INF, int FPr>
__global__ void kan_conv(const float* __restrict__ in,
                         const float* __restrict__ wp,
                         float* __restrict__ out,
                         int B, int H, int W, int Ho, int Wo, int OUT) {
    extern __shared__ float phi[];  // [16][FPr]
    const int N    = B * Ho * Wo;
    const int pos0 = blockIdx.x * 16;

    // ---- stage 1: build phi for 16 positions ----
    const int E = 16 * INF;
    for (int e = threadIdx.x; e < E; e += blockDim.x) {
        int pos = e / INF;
        int i   = e - pos * INF;
        int gp  = pos0 + pos;
        float x = 0.0f;
        if (gp < N) {
            int b  = gp / (Ho * Wo);
            int r  = gp - b * Ho * Wo;
            int ho = r / Wo;
            int wo = r - ho * Wo;
            int c  = i / (K * K);
            int rr = i - c * K * K;
            int kh = rr / K;
            int kw = rr - kh * K;
            int hin = ho * S - P + kh;
            int win = wo * S - P + kw;
            if (hin >= 0 && hin < H && win >= 0 && win < W)
                x = in[((b * CIN + c) * H + hin) * W + win];
        }
        float ph[9];
        eval_phi(x, ph);
        float* dst = phi + pos * FPr + i * 9;
#pragma unroll
        for (int r2 = 0; r2 < 9; r2++) dst[r2] = ph[r2];
    }
    // zero float4 padding tail
    for (int f = INF * 9 + (int)threadIdx.x; f < FPr; f += blockDim.x) {
#pragma unroll
        for (int pos = 0; pos < 16; pos++) phi[pos * FPr + f] = 0.0f;
    }
    __syncthreads();

    // ---- stage 2: GEMM (pos,out) pairs ----
    int ol  = threadIdx.x & 15;
    int pos = threadIdx.x >> 4;
    int og  = blockIdx.y * 16 + ol;

    const float4* pr = (const float4*)(phi + pos * FPr);
    const float4* wr = (const float4*)(wp + og * FPr);
    float4 acc = make_float4(0.f, 0.f, 0.f, 0.f);
#pragma unroll 4
    for (int f = 0; f < FPr / 4; f++) {
        float4 p = pr[f];
        float4 w = wr[f];
        acc.x = fmaf(p.x, w.x, acc.x);
        acc.y = fmaf(p.y, w.y, acc.y);
        acc.z = fmaf(p.z, w.z, acc.z);
        acc.w = fmaf(p.w, w.w, acc.w);
    }
    float a = (acc.x + acc.y) + (acc.z + acc.w);

    int gp = pos0 + pos;
    if (gp < N) {
        int b  = gp / (Ho * Wo);
        int r  = gp - b * Ho * Wo;
        int ho = r / Wo;
        int wo = r - ho * Wo;
        out[((b * OUT + og) * Ho + ho) * Wo + wo] = fmaxf(a, 0.0f);
    }
}

// ---------------------------------------------------------------------------
// 2x2 max pool (inputs already relu'd)
// ---------------------------------------------------------------------------
__global__ void maxpool2(const float* __restrict__ in, float* __restrict__ out,
                         int B, int C, int H, int W) {
    int Ho = H / 2, Wo = W / 2;
    int n = B * C * Ho * Wo;
    int idx = blockIdx.x * blockDim.x + threadIdx.x;
    if (idx >= n) return;
    int wo = idx % Wo;
    int t  = idx / Wo;
    int ho = t % Ho;
    t /= Ho;
    int c = t % C;
    int b = t / C;
    const float* p = in + ((b * C + c) * H + ho * 2) * W + wo * 2;
    out[idx] = fmaxf(fmaxf(p[0], p[1]), fmaxf(p[W], p[W + 1]));
}

// ---------------------------------------------------------------------------
// Head: global avg pool (7x7) + KAN linear 64 -> 200. One block.
// ---------------------------------------------------------------------------
__global__ void classifier_kernel(const float* __restrict__ act,  // (8,64,7,7)
                                  const float* __restrict__ wp,   // (200,FPC)
                                  float* __restrict__ out) {      // (8,200)
    __shared__ float mean[8 * 64];
    __shared__ float phi[8 * FPC];
    int tid = threadIdx.x;

    for (int e = tid; e < 512; e += 256) {
        const float* p = act + e * 49;
        float s = 0.0f;
#pragma unroll
        for (int i = 0; i < 49; i++) s += p[i];
        mean[e] = s * (1.0f / 49.0f);
    }
    __syncthreads();
    for (int e = tid; e < 512; e += 256) {
        int b = e >> 6;
        int c = e & 63;
        float ph[9];
        eval_phi(mean[e], ph);
        float* dst = phi + b * FPC + c * 9;
#pragma unroll
        for (int r = 0; r < 9; r++) dst[r] = ph[r];
    }
    __syncthreads();
    for (int p = tid; p < 1600; p += 256) {
        int b = p / 200;
        int o = p - b * 200;
        const float4* pr = (const float4*)(phi + b * FPC);
        const float4* wr = (const float4*)(wp + o * FPC);
        float4 acc = make_float4(0.f, 0.f, 0.f, 0.f);
#pragma unroll 4
        for (int f = 0; f < FPC / 4; f++) {
            float4 pv = pr[f];
            float4 wv = wr[f];
            acc.x = fmaf(pv.x, wv.x, acc.x);
            acc.y = fmaf(pv.y, wv.y, acc.y);
            acc.z = fmaf(pv.z, wv.z, acc.z);
            acc.w = fmaf(pv.w, wv.w, acc.w);
        }
        out[b * 200 + o] = (acc.x + acc.y) + (acc.z + acc.w);
    }
}

// ---------------------------------------------------------------------------
// Host launcher
// ---------------------------------------------------------------------------
static void* sym_addr(const void* symbol) {
    void* p = nullptr;
    cudaGetSymbolAddress(&p, symbol);
    return p;
}

extern "C" void kernel_launch(void* const* d_in, const int* in_sizes, int n_in,
                              void* d_out, int out_size) {
    const float* x   = (const float*)d_in[0];
    const float* bw0 = (const float*)d_in[1];
    const float* sw0 = (const float*)d_in[2];
    const float* sc0 = (const float*)d_in[3];
    const float* bw1 = (const float*)d_in[4];
    const float* sw1 = (const float*)d_in[5];
    const float* sc1 = (const float*)d_in[6];
    const float* bw2 = (const float*)d_in[7];
    const float* sw2 = (const float*)d_in[8];
    const float* sc2 = (const float*)d_in[9];
    const float* bwc = (const float*)d_in[10];
    const float* swc = (const float*)d_in[11];
    const float* scc = (const float*)d_in[12];
    float* out = (float*)d_out;

    float* wp0 = (float*)sym_addr(g_wp0);
    float* wp1 = (float*)sym_addr(g_wp1);
    float* wp2 = (float*)sym_addr(g_wp2);
    float* wpc = (float*)sym_addr(g_wpc);
    float* a0  = (float*)sym_addr(g_a0);
    float* p0  = (float*)sym_addr(g_p0);
    float* a1  = (float*)sym_addr(g_a1);
    float* p1  = (float*)sym_addr(g_p1);
    float* a2  = (float*)sym_addr(g_a2);

    // weight packing
    pack_kernel<<<(16 * FP0 + 255) / 256, 256>>>(bw0, sw0, sc0, wp0, 16, 147, FP0);
    pack_kernel<<<(32 * FP1 + 255) / 256, 256>>>(bw1, sw1, sc1, wp1, 32, 144, FP1);
    pack_kernel<<<(64 * FP2 + 255) / 256, 256>>>(bw2, sw2, sc2, wp2, 64, 288, FP2);
    pack_kernel<<<(200 * FPC + 255) / 256, 256>>>(bwc, swc, scc, wpc, 200, 64, FPC);

    // layer 0
    {
        auto k = kan_conv<3, 7, 2, 3, 147, FP0>;
        int smem = 16 * FP0 * 4;
        cudaFuncSetAttribute((const void*)k, cudaFuncAttributeMaxDynamicSharedMemorySize, smem);
        dim3 grid(8 * 112 * 112 / 16, 1);
        k<<<grid, 256, smem>>>(x, wp0, a0, 8, 224, 224, 112, 112, 16);
        maxpool2<<<(8 * 16 * 56 * 56 + 255) / 256, 256>>>(a0, p0, 8, 16, 112, 112);
    }
    // layer 1
    {
        auto k = kan_conv<16, 3, 2, 1, 144, FP1>;
        int smem = 16 * FP1 * 4;
        cudaFuncSetAttribute((const void*)k, cudaFuncAttributeMaxDynamicSharedMemorySize, smem);
        dim3 grid(8 * 28 * 28 / 16, 2);
        k<<<grid, 256, smem>>>(p0, wp1, a1, 8, 56, 56, 28, 28, 32);
        maxpool2<<<(8 * 32 * 14 * 14 + 255) / 256, 256>>>(a1, p1, 8, 32, 28, 28);
    }
    // layer 2
    {
        auto k = kan_conv<32, 3, 2, 1, 288, FP2>;
        int smem = 16 * FP2 * 4;
        cudaFuncSetAttribute((const void*)k, cudaFuncAttributeMaxDynamicSharedMemorySize, smem);
        dim3 grid((8 * 7 * 7 + 15) / 16, 4);
        k<<<grid, 256, smem>>>(p1, wp2, a2, 8, 14, 14, 7, 7, 64);
    }
    // head
    classifier_kernel<<<1, 256>>>(a2, wpc, out);

    (void)in_sizes; (void)n_in; (void)out_size;
}

// round 3
// speedup vs baseline: 3.5033x; 3.5033x over previous
#include <cuda_runtime.h>
#include <math.h>

// ---------------------------------------------------------------------------
// KANConvNet, round 2: weights-in-SMEM (broadcast), sparse 5-term B-spline
// accumulation over padded 15-row weight layout, packed f32x2 FMA.
//
//   L0: cin=3,  cout=16, k=7, s=2, p=3 : 224 -> 112 -> pool 56
//   L1: cin=16, cout=32, k=3, s=2, p=1 : 56  -> 28  -> pool 14
//   L2: cin=32, cout=64, k=3, s=2, p=1 : 14  -> 7
//   head: mean(7x7) -> kan_linear(64 -> 200)
//
// Packed weights per layer, layout [i][15][OUT]:
//   r'=0      : base_w[o][i]          (multiplied by silu(x_i))
//   r'=4+j    : sw[o][i][j]*sc[o][i]  (j=0..7)
//   r' 1..3, 12..14 : zero pad rows
// For x with knot cell m = floor((x+2.2)/0.4) in [0,10], the 4 nonzero bases
// are rows m+1..m+4 with cardinal cubic weights w0..w3. Out-of-range x -> w=0.
// ---------------------------------------------------------------------------

__device__ float g_wp0[147 * 15 * 16];
__device__ float g_wp1[144 * 15 * 32];
__device__ float g_wp2[288 * 15 * 64];
__device__ float g_wpc[64  * 15 * 200];

__device__ float g_a0[8 * 16 * 112 * 112];
__device__ float g_p0[8 * 16 * 56 * 56];
__device__ float g_a1[8 * 32 * 28 * 28];
__device__ float g_p1[8 * 32 * 14 * 14];
__device__ float g_a2[8 * 64 * 7 * 7];

// ---------------- packed f32x2 helpers ----------------
__device__ __forceinline__ long long pk2(float a) {
    long long r;
    asm("mov.b64 %0, {%1, %1};" : "=l"(r) : "f"(a));
    return r;
}
__device__ __forceinline__ long long ffma2(long long a, long long b, long long c) {
    long long d;
    asm("fma.rn.f32x2 %0, %1, %2, %3;" : "=l"(d) : "l"(a), "l"(b), "l"(c));
    return d;
}
__device__ __forceinline__ float2 upk2(long long a) {
    float x, y;
    asm("mov.b64 {%0, %1}, %2;" : "=f"(x), "=f"(y) : "l"(a));
    return make_float2(x, y);
}

// ---------------- coefficient evaluation ----------------
// c0 = silu(x); w0..w3 = cardinal cubic weights for rows m+1..m+4.
__device__ __forceinline__ void eval_c5(float x, float& c0,
                                        float& w0, float& w1, float& w2, float& w3,
                                        int& m) {
    float sig = 1.0f / (1.0f + __expf(-x));
    c0 = x * sig;
    float t  = fmaf(x, 2.5f, 5.5f);     // (x + 2.2) / 0.4
    float mf = floorf(t);
    bool inr = (mf >= 0.0f) && (mf <= 10.0f);
    mf = fminf(fmaxf(mf, 0.0f), 10.0f);
    float u  = t - mf;
    float u2 = u * u;
    float u3 = u2 * u;
    float om = 1.0f - u;
    const float s6 = 1.0f / 6.0f;
    float a0 = s6 * om * om * om;
    float a1 = s6 * fmaf(3.0f, u3, fmaf(-6.0f, u2, 4.0f));
    float a2 = s6 * fmaf(-3.0f, u3, fmaf(3.0f, u2, fmaf(3.0f, u, 1.0f)));
    float a3 = s6 * u3;
    w0 = inr ? a0 : 0.0f;
    w1 = inr ? a1 : 0.0f;
    w2 = inr ? a2 : 0.0f;
    w3 = inr ? a3 : 0.0f;
    m = (int)mf;
}

// ---------------- weight packing ----------------
__global__ void pack_kernel(const float* __restrict__ bw,
                            const float* __restrict__ sw,
                            const float* __restrict__ sc,
                            float* __restrict__ wp,
                            int OUT, int IN) {
    int idx = blockIdx.x * blockDim.x + threadIdx.x;
    int total = IN * 15 * OUT;
    if (idx >= total) return;
    int i   = idx / (15 * OUT);
    int rem = idx - i * 15 * OUT;
    int r   = rem / OUT;
    int o   = rem - r * OUT;
    int oi  = o * IN + i;
    float v = 0.0f;
    if (r == 0)               v = bw[oi];
    else if (r >= 4 && r < 12) v = sw[oi * 8 + (r - 4)] * sc[oi];
    wp[idx] = v;
}

// ---------------------------------------------------------------------------
// Fused KAN conv layer. One thread = one spatial position, OT outputs in regs.
// Weights for this block's out-tile live in SMEM (all-lane broadcast reads
// for the base row; 4-way-max divergent rows for the spline window).
// ---------------------------------------------------------------------------
template <int CIN, int K, int S, int P, int OUT, int OT, int T>
__global__ void __launch_bounds__(T)
kan_conv(const float* __restrict__ in,
         const float* __restrict__ wp,
         float* __restrict__ out,
         int B, int H, int W, int Ho, int Wo) {
    extern __shared__ float swm[];   // [INF][15][OT]
    const int INF = CIN * K * K;
    const int ot  = blockIdx.y;

    // cooperative weight-tile load
    for (int idx = threadIdx.x; idx < INF * 15 * OT; idx += T) {
        int i   = idx / (15 * OT);
        int rem = idx - i * 15 * OT;
        int r   = rem / OT;
        int o   = rem - r * OT;
        swm[idx] = wp[(i * 15 + r) * OUT + ot * OT + o];
    }
    __syncthreads();

    const int N  = B * Ho * Wo;
    int gp       = blockIdx.x * T + threadIdx.x;
    bool valid   = gp < N;
    int gpc      = valid ? gp : 0;
    int b  = gpc / (Ho * Wo);
    int rr = gpc - b * Ho * Wo;
    int ho = rr / Wo;
    int wo = rr - ho * Wo;
    int hb = ho * S - P;
    int wb = wo * S - P;
    const float* inb = in + (long long)b * CIN * H * W;

    long long acc[OT / 2];
#pragma unroll
    for (int k = 0; k < OT / 2; k++) acc[k] = 0LL;

    const float* swr = swm;
#pragma unroll 1
    for (int c = 0; c < CIN; c++) {
#pragma unroll 1
        for (int kh = 0; kh < K; kh++) {
            int hin = hb + kh;
            const float* row = inb + ((long long)c * H + hin) * W;
            bool hok = valid && (hin >= 0) && (hin < H);
#pragma unroll
            for (int kw = 0; kw < K; kw++) {
                int win = wb + kw;
                float x = 0.0f;
                if (hok && win >= 0 && win < W) x = row[win];

                float c0, w0, w1, w2, w3; int m;
                eval_c5(x, c0, w0, w1, w2, w3, m);

                long long C0 = pk2(c0);
                long long W0 = pk2(w0);
                long long W1 = pk2(w1);
                long long W2 = pk2(w2);
                long long W3 = pk2(w3);

                const ulonglong2* r0 = (const ulonglong2*)swr;
                const ulonglong2* rs = (const ulonglong2*)(swr + (m + 1) * OT);

#pragma unroll
                for (int q = 0; q < OT / 4; q++) {
                    ulonglong2 a = r0[q];
                    acc[2 * q]     = ffma2(C0, (long long)a.x, acc[2 * q]);
                    acc[2 * q + 1] = ffma2(C0, (long long)a.y, acc[2 * q + 1]);
                }
#pragma unroll
                for (int tt = 0; tt < 4; tt++) {
                    long long Wt = (tt == 0) ? W0 : (tt == 1) ? W1 : (tt == 2) ? W2 : W3;
#pragma unroll
                    for (int q = 0; q < OT / 4; q++) {
                        ulonglong2 a = rs[tt * (OT / 4) + q];
                        acc[2 * q]     = ffma2(Wt, (long long)a.x, acc[2 * q]);
                        acc[2 * q + 1] = ffma2(Wt, (long long)a.y, acc[2 * q + 1]);
                    }
                }
                swr += 15 * OT;
            }
        }
    }

    if (valid) {
        long long HW = (long long)Ho * Wo;
        float* ob = out + ((long long)(b * OUT + ot * OT) * Ho + ho) * Wo + wo;
#pragma unroll
        for (int k = 0; k < OT / 2; k++) {
            float2 v = upk2(acc[k]);
            ob[(2 * k) * HW]     = fmaxf(v.x, 0.0f);
            ob[(2 * k + 1) * HW] = fmaxf(v.y, 0.0f);
        }
    }
}

// ---------------------------------------------------------------------------
// 2x2 max pool
// ---------------------------------------------------------------------------
__global__ void maxpool2(const float* __restrict__ in, float* __restrict__ out,
                         int B, int C, int H, int W) {
    int Ho = H / 2, Wo = W / 2;
    int n = B * C * Ho * Wo;
    int idx = blockIdx.x * blockDim.x + threadIdx.x;
    if (idx >= n) return;
    int wo = idx % Wo;
    int t  = idx / Wo;
    int ho = t % Ho;
    t /= Ho;
    int c = t % C;
    int b = t / C;
    const float* p = in + ((long long)(b * C + c) * H + ho * 2) * W + wo * 2;
    out[idx] = fmaxf(fmaxf(p[0], p[1]), fmaxf(p[W], p[W + 1]));
}

// ---------------------------------------------------------------------------
// Head: mean(7x7) -> KAN linear 64 -> 200.  8 blocks, each owns 25 outputs.
// ---------------------------------------------------------------------------
__global__ void classifier_kernel(const float* __restrict__ act,   // (8,64,7,7)
                                  const float* __restrict__ wp,    // [64][15][200]
                                  float* __restrict__ out) {       // (8,200)
    __shared__ float mean[512];
    __shared__ float cs[512 * 5];
    __shared__ int   cm[512];
    int tid = threadIdx.x;
    int ot  = blockIdx.x;

    for (int e = tid; e < 512; e += 256) {
        const float* p = act + e * 49;
        float s = 0.0f;
#pragma unroll
        for (int i = 0; i < 49; i++) s += p[i];
        mean[e] = s * (1.0f / 49.0f);
    }
    __syncthreads();
    for (int e = tid; e < 512; e += 256) {
        float c0, w0, w1, w2, w3; int m;
        eval_c5(mean[e], c0, w0, w1, w2, w3, m);
        cs[e * 5 + 0] = c0;
        cs[e * 5 + 1] = w0;
        cs[e * 5 + 2] = w1;
        cs[e * 5 + 3] = w2;
        cs[e * 5 + 4] = w3;
        cm[e] = m;
    }
    __syncthreads();
    if (tid < 200) {
        int b = tid / 25;
        int o = ot * 25 + tid % 25;
        float acc = 0.0f;
#pragma unroll 1
        for (int i = 0; i < 64; i++) {
            const float* cp = &cs[(b * 64 + i) * 5];
            int m = cm[b * 64 + i];
            const float* wr = wp + (i * 15) * 200 + o;
            acc = fmaf(cp[0], wr[0], acc);
            acc = fmaf(cp[1], wr[(m + 1) * 200], acc);
            acc = fmaf(cp[2], wr[(m + 2) * 200], acc);
            acc = fmaf(cp[3], wr[(m + 3) * 200], acc);
            acc = fmaf(cp[4], wr[(m + 4) * 200], acc);
        }
        out[b * 200 + o] = acc;
    }
}

// ---------------------------------------------------------------------------
// Host launcher
// ---------------------------------------------------------------------------
static void* sym_addr(const void* symbol) {
    void* p = nullptr;
    cudaGetSymbolAddress(&p, symbol);
    return p;
}

extern "C" void kernel_launch(void* const* d_in, const int* in_sizes, int n_in,
                              void* d_out, int out_size) {
    const float* x   = (const float*)d_in[0];
    const float* bw0 = (const float*)d_in[1];
    const float* sw0 = (const float*)d_in[2];
    const float* sc0 = (const float*)d_in[3];
    const float* bw1 = (const float*)d_in[4];
    const float* sw1 = (const float*)d_in[5];
    const float* sc1 = (const float*)d_in[6];
    const float* bw2 = (const float*)d_in[7];
    const float* sw2 = (const float*)d_in[8];
    const float* sc2 = (const float*)d_in[9];
    const float* bwc = (const float*)d_in[10];
    const float* swc = (const float*)d_in[11];
    const float* scc = (const float*)d_in[12];
    float* out = (float*)d_out;

    float* wp0 = (float*)sym_addr(g_wp0);
    float* wp1 = (float*)sym_addr(g_wp1);
    float* wp2 = (float*)sym_addr(g_wp2);
    float* wpc = (float*)sym_addr(g_wpc);
    float* a0  = (float*)sym_addr(g_a0);
    float* p0  = (float*)sym_addr(g_p0);
    float* a1  = (float*)sym_addr(g_a1);
    float* p1  = (float*)sym_addr(g_p1);
    float* a2  = (float*)sym_addr(g_a2);

    pack_kernel<<<(147 * 15 * 16  + 255) / 256, 256>>>(bw0, sw0, sc0, wp0, 16, 147);
    pack_kernel<<<(144 * 15 * 32  + 255) / 256, 256>>>(bw1, sw1, sc1, wp1, 32, 144);
    pack_kernel<<<(288 * 15 * 64  + 255) / 256, 256>>>(bw2, sw2, sc2, wp2, 64, 288);
    pack_kernel<<<(64  * 15 * 200 + 255) / 256, 256>>>(bwc, swc, scc, wpc, 200, 64);

    // layer 0: OUT=16, OT=8, 2 out-tiles, 256 thr, smem = 147*15*8*4 = 70560
    {
        auto k = kan_conv<3, 7, 2, 3, 16, 8, 256>;
        int smem = 147 * 15 * 8 * 4;
        cudaFuncSetAttribute((const void*)k, cudaFuncAttributeMaxDynamicSharedMemorySize, smem);
        dim3 grid(8 * 112 * 112 / 256, 2);
        k<<<grid, 256, smem>>>(x, wp0, a0, 8, 224, 224, 112, 112);
        maxpool2<<<(8 * 16 * 56 * 56 + 255) / 256, 256>>>(a0, p0, 8, 16, 112, 112);
    }
    // layer 1: OUT=32, OT=8, 4 out-tiles, smem = 144*15*8*4 = 69120
    {
        auto k = kan_conv<16, 3, 2, 1, 32, 8, 256>;
        int smem = 144 * 15 * 8 * 4;
        cudaFuncSetAttribute((const void*)k, cudaFuncAttributeMaxDynamicSharedMemorySize, smem);
        dim3 grid((8 * 28 * 28 + 255) / 256, 4);
        k<<<grid, 256, smem>>>(p0, wp1, a1, 8, 56, 56, 28, 28);
        maxpool2<<<(8 * 32 * 14 * 14 + 255) / 256, 256>>>(a1, p1, 8, 32, 28, 28);
    }
    // layer 2: OUT=64, OT=8, 8 out-tiles, 128 thr, smem = 288*15*8*4 = 138240
    {
        auto k = kan_conv<32, 3, 2, 1, 64, 8, 128>;
        int smem = 288 * 15 * 8 * 4;
        cudaFuncSetAttribute((const void*)k, cudaFuncAttributeMaxDynamicSharedMemorySize, smem);
        dim3 grid((8 * 7 * 7 + 127) / 128, 8);
        k<<<grid, 128, smem>>>(p1, wp2, a2, 8, 14, 14, 7, 7);
    }
    classifier_kernel<<<8, 256>>>(a2, wpc, out);

    (void)in_sizes; (void)n_in; (void)out_size;
}